// round 9
// baseline (speedup 1.0000x reference)
#include <cuda_runtime.h>

// ---------------- problem constants (fixed by dataset) ----------------
#define NPIX 147456        // 384*384
#define W384 384
#define NNZC 1474560       // NPIX * 10
#define NLOC 73728         // NPIX/2
#define KIU  5
#define CG_STEPS 30

#define TPB   512
#define NBLK  288          // 288*512 == NPIX exactly
#define MPB   256          // matting/IU pixels per block (NLOC / NBLK)
#define NWARP (TPB / 32)
#define EPB   (NNZC / NBLK)   // COO entries per block in setup = 5120
#define MAXWIN 2048        // smem window capacity (floats)

// ---------------- device scratch (static only) ----------------
__device__ int2  g_pairR[NNZC];        // CSR-sorted {col, val-bits}
__device__ int2  g_pairC[NNZC];        // CSC-sorted {row, val-bits}
__device__ int   g_ptrR[NPIX + 1];
__device__ int   g_ptrC[NPIX + 1];
__device__ int   g_ptrM[NPIX];
__device__ int   g_ptrI[NPIX];
__device__ int   g_cntR[NPIX];
__device__ int   g_cntC[NPIX];
__device__ int   g_cntM[NPIX];
__device__ int   g_cntI[NPIX];
__device__ int   g_tmpR[NPIX];
__device__ int   g_tmpC[NPIX];
__device__ int   g_tmpM[NPIX];
__device__ int   g_tmpI[NPIX];
__device__ int4  g_btot4[NBLK];

__device__ int   g_mInd[NLOC];         // matting pixel indices, sorted ascending
__device__ int   g_iInd[NLOC];         // IU pixel indices, sorted ascending
__device__ float g_rs_cm[NPIX];
__device__ float g_D[NPIX];
__device__ float g_S45[45 * NLOC];     // symmetric matting blocks [t*NLOC + sorted_pos]
__device__ float g_Wiu[KIU * NLOC];    // [l*NLOC + sorted_pos]
__device__ int   g_iuNbT[KIU * NLOC];  // [l*NLOC + sorted_pos]
__device__ float g_r[NPIX];
__device__ float g_w[NPIX];            // accumulates A*r (atomic; zeroed each iter)
__device__ float g_Lv[NPIX];
__device__ double2 g_dot1[NBLK];       // {gamma, delta partial P1}
__device__ double  g_dot2[NBLK];       // delta partials P2

__device__ unsigned g_count;
__device__ volatile unsigned g_sense;
__device__ unsigned g_exit;

// ---------------- helpers ----------------
__device__ __forceinline__ int OFF9(int i) {
    int a = i / 3, b = i % 3;
    return (a - 1) + (b - 1) * W384;
}
__device__ __forceinline__ int TIDX(int i, int j) {
    return 9 * i - (i * (i - 1)) / 2 + (j - i);
}

__device__ __forceinline__ double bred(double v, double* sm) {
    int lane = threadIdx.x & 31, w = threadIdx.x >> 5;
    #pragma unroll
    for (int o = 16; o > 0; o >>= 1) v += __shfl_down_sync(0xffffffffu, v, o);
    if (lane == 0) sm[w] = v;
    __syncthreads();
    if (w == 0) {
        v = (lane < NWARP) ? sm[lane] : 0.0;
        #pragma unroll
        for (int o = 8; o > 0; o >>= 1) v += __shfl_down_sync(0xffffu, v, o);
    }
    __syncthreads();
    return v;
}

__device__ __forceinline__ double2 bred2(double a, double b, double2* sm2) {
    int lane = threadIdx.x & 31, w = threadIdx.x >> 5;
    #pragma unroll
    for (int o = 16; o > 0; o >>= 1) {
        a += __shfl_down_sync(0xffffffffu, a, o);
        b += __shfl_down_sync(0xffffffffu, b, o);
    }
    if (lane == 0) sm2[w] = make_double2(a, b);
    __syncthreads();
    if (w == 0) {
        double2 t = (lane < NWARP) ? sm2[lane] : make_double2(0.0, 0.0);
        a = t.x; b = t.y;
        #pragma unroll
        for (int o = 8; o > 0; o >>= 1) {
            a += __shfl_down_sync(0xffffu, a, o);
            b += __shfl_down_sync(0xffffu, b, o);
        }
    }
    __syncthreads();
    return make_double2(a, b);
}

__device__ __forceinline__ void gbar(unsigned &ep) {
    ep++;
    __syncthreads();
    if (threadIdx.x == 0) {
        __threadfence();
        if (atomicAdd(&g_count, 1u) == NBLK - 1) {
            g_count = 0;
            __threadfence();
            g_sense = ep;
        } else {
            while (g_sense != ep) { __nanosleep(32); }
            __threadfence();
        }
    }
    __syncthreads();
}

// ---------------- single persistent kernel: setup + CG ----------------
__global__ void __launch_bounds__(TPB, 2) k_all(
    float* __restrict__ x,
    const float* __restrict__ CMw,  const float* __restrict__ LOCw,
    const float* __restrict__ IUw,  const float* __restrict__ KUw,
    const float* __restrict__ lmbda,
    const float* __restrict__ kToUcf, const float* __restrict__ known,
    const float* __restrict__ kToU, const float* __restrict__ Wd,
    const float* __restrict__ LF,   const float* __restrict__ IUf,
    const int* __restrict__ wrow,   const int* __restrict__ wcol,
    const int* __restrict__ locInd, const int* __restrict__ iuInd,
    const int* __restrict__ iuNb)
{
    __shared__ int4   s_scan4[TPB];
    __shared__ float  s_rwin[MAXWIN];
    __shared__ float  s_wwin[MAXWIN];
    __shared__ double2 sm2[NWARP];
    __shared__ double sred[NWARP];
    __shared__ int4   s_off4;
    __shared__ double s_alpha, s_beta, s_gamma_prev, s_alpha_prev;

    const int tid  = threadIdx.x;
    const int gtid = blockIdx.x * TPB + tid;     // always < NPIX
    const int m    = blockIdx.x * MPB + tid;     // sorted matting/IU slot if tid < MPB
    const int ebase = blockIdx.x * EPB;
    unsigned ep = 0;

    // ---- P0: zero working state
    g_cntR[gtid] = 0; g_cntC[gtid] = 0; g_cntM[gtid] = 0; g_cntI[gtid] = 0;
    g_tmpR[gtid] = 0; g_tmpC[gtid] = 0; g_tmpM[gtid] = 0; g_tmpI[gtid] = 0;
    g_rs_cm[gtid] = 0.f; g_D[gtid] = 0.f; g_w[gtid] = 0.f;
    gbar(ep);

    // ---- S1: counts (CM rows/cols, matting ind, IU ind) + rowsums + data term
    for (int e = tid; e < EPB; e += TPB) {
        int k = ebase + e;
        int r = wrow[k], c = wcol[k];
        float cv = CMw[r] * Wd[k];
        atomicAdd(&g_rs_cm[r], cv);
        atomicAdd(&g_cntR[r], 1);
        atomicAdd(&g_cntC[c], 1);
    }
    if (gtid < NLOC) {
        atomicAdd(&g_cntM[locInd[gtid]], 1);
        atomicAdd(&g_cntI[iuInd[gtid]], 1);
    }
    float r_reg;
    {
        float dk = KUw[gtid] * kToUcf[gtid] + lmbda[0] * known[gtid];
        r_reg = dk * kToU[gtid];
        g_r[gtid] = r_reg;
        atomicAdd(&g_D[gtid], dk);
    }
    gbar(ep);

    // ---- S2: block-local inclusive scan of {cntR, cntC, cntM, cntI}
    int4 myc = make_int4(g_cntR[gtid], g_cntC[gtid], g_cntM[gtid], g_cntI[gtid]);
    s_scan4[tid] = myc;
    __syncthreads();
    for (int o = 1; o < TPB; o <<= 1) {
        int4 t = (tid >= o) ? s_scan4[tid - o] : make_int4(0, 0, 0, 0);
        __syncthreads();
        s_scan4[tid].x += t.x; s_scan4[tid].y += t.y;
        s_scan4[tid].z += t.z; s_scan4[tid].w += t.w;
        __syncthreads();
    }
    int4 incl = s_scan4[tid];
    int exR = incl.x - myc.x, exC = incl.y - myc.y;
    int exM = incl.z - myc.z, exI = incl.w - myc.w;
    if (tid == TPB - 1) g_btot4[blockIdx.x] = incl;
    gbar(ep);

    // ---- S3: cross-block offsets + write ptr arrays
    {
        int4 v = (tid < blockIdx.x) ? g_btot4[tid] : make_int4(0, 0, 0, 0);
        int lane = tid & 31, w = tid >> 5;
        #pragma unroll
        for (int o = 16; o > 0; o >>= 1) {
            v.x += __shfl_down_sync(0xffffffffu, v.x, o);
            v.y += __shfl_down_sync(0xffffffffu, v.y, o);
            v.z += __shfl_down_sync(0xffffffffu, v.z, o);
            v.w += __shfl_down_sync(0xffffffffu, v.w, o);
        }
        __shared__ int4 sw[NWARP];
        if (lane == 0) sw[w] = v;
        __syncthreads();
        if (w == 0) {
            int4 t = (lane < NWARP) ? sw[lane] : make_int4(0, 0, 0, 0);
            #pragma unroll
            for (int o = 8; o > 0; o >>= 1) {
                t.x += __shfl_down_sync(0xffffu, t.x, o);
                t.y += __shfl_down_sync(0xffffu, t.y, o);
                t.z += __shfl_down_sync(0xffffu, t.z, o);
                t.w += __shfl_down_sync(0xffffu, t.w, o);
            }
            if (lane == 0) s_off4 = t;
        }
        __syncthreads();
        g_ptrR[gtid] = exR + s_off4.x;
        g_ptrC[gtid] = exC + s_off4.y;
        g_ptrM[gtid] = exM + s_off4.z;
        g_ptrI[gtid] = exI + s_off4.w;
        if (gtid == 0) { g_ptrR[NPIX] = NNZC; g_ptrC[NPIX] = NNZC; }
    }
    gbar(ep);

    // ---- S4: scatter CM pairs; matting blocks + IU weights at SORTED positions
    for (int e = tid; e < EPB; e += TPB) {
        int k = ebase + e;
        int r = wrow[k], c = wcol[k];
        int vb = __float_as_int(CMw[r] * Wd[k]);
        int p1 = g_ptrR[r] + atomicAdd(&g_tmpR[r], 1);
        g_pairR[p1] = make_int2(c, vb);
        int p2 = g_ptrC[c] + atomicAdd(&g_tmpC[c], 1);
        g_pairC[p2] = make_int2(r, vb);
    }
    if (gtid < NLOC) {
        int m0 = gtid;
        // matting: compute symmetric block from LF (coalesced in m0), write at sorted pos
        {
            int ind = locInd[m0];
            int pos = g_ptrM[ind] + atomicAdd(&g_tmpM[ind], 1);
            g_mInd[pos] = ind;
            float w = LOCw[ind];
            float rs[9];
            #pragma unroll
            for (int q = 0; q < 9; q++) rs[q] = 0.f;
            #pragma unroll
            for (int a = 0; a < 9; a++) {
                #pragma unroll
                for (int b2 = a; b2 < 9; b2++) {
                    float s = 0.5f * w * (LF[(b2 * 9 + a) * NLOC + m0] + LF[(a * 9 + b2) * NLOC + m0]);
                    g_S45[TIDX(a, b2) * NLOC + pos] = s;
                    rs[a] += s;
                    if (b2 > a) rs[b2] += s;
                }
            }
            #pragma unroll
            for (int q = 0; q < 9; q++) atomicAdd(&g_D[ind + OFF9(q)], rs[q]);
        }
        // IU: write at sorted pos
        {
            int ind2 = iuInd[m0];
            int pos = g_ptrI[ind2] + atomicAdd(&g_tmpI[ind2], 1);
            g_iInd[pos] = ind2;
            float w = IUw[ind2];
            #pragma unroll
            for (int l = 0; l < KIU; l++) {
                float wv = 0.5f * w * IUf[m0 * KIU + l];
                int nb = iuNb[m0 * KIU + l];
                g_Wiu[l * NLOC + pos] = wv;
                g_iuNbT[l * NLOC + pos] = nb;
                atomicAdd(&g_D[ind2], wv);
                atomicAdd(&g_D[nb], wv);
            }
        }
    }
    gbar(ep);

    // ---- loop invariants
    const float rc = g_rs_cm[gtid];
    const float Di = g_D[gtid];
    const int rb0 = g_ptrR[gtid], rb1 = g_ptrR[gtid + 1];
    const int cb0 = g_ptrC[gtid], cb1 = g_ptrC[gtid + 1];
    // matting window bounds for this block (sorted inds -> contiguous span)
    int w0, wsz;
    {
        int lo = g_mInd[blockIdx.x * MPB]            - (W384 + 1);
        int hi = g_mInd[blockIdx.x * MPB + MPB - 1]  + (W384 + 1);
        w0 = lo; wsz = hi - lo + 1;
    }
    const bool useWin = (wsz <= MAXWIN);
    float p_reg = 0.f, s_reg = 0.f, x_reg = 0.f;

    // ---- CG iterations (single-reduction Chronopoulos-Gear)
    for (int it = 0; it < CG_STEPS; ++it) {
        // Phase 1: CSR gather -> Lv; base term; matting via smem window
        {
            if (useWin) {
                for (int i = tid; i < wsz; i += TPB) {
                    s_rwin[i] = g_r[w0 + i];
                    s_wwin[i] = 0.f;
                }
            }
            __syncthreads();
            double dG = (double)r_reg * (double)r_reg;
            double dD1;
            {
                float acc = 0.f;
                int k = rb0;
                for (; k + 4 <= rb1; k += 4) {
                    int2 e0 = g_pairR[k],     e1 = g_pairR[k + 1];
                    int2 e2 = g_pairR[k + 2], e3 = g_pairR[k + 3];
                    acc += __int_as_float(e0.y) * g_r[e0.x]
                         + __int_as_float(e1.y) * g_r[e1.x]
                         + __int_as_float(e2.y) * g_r[e2.x]
                         + __int_as_float(e3.y) * g_r[e3.x];
                }
                for (; k < rb1; k++) {
                    int2 e = g_pairR[k];
                    acc += __int_as_float(e.y) * g_r[e.x];
                }
                float lv = rc * r_reg - acc;
                g_Lv[gtid] = lv;
                float wi = rc * lv + Di * r_reg;
                atomicAdd(&g_w[gtid], wi);
                dD1 = (double)r_reg * (double)wi;
            }
            if (tid < MPB) {
                int ind = g_mInd[m];
                float pn[9], acc9[9];
                if (useWin) {
                    int base = ind - w0;
                    #pragma unroll
                    for (int j = 0; j < 9; j++) { pn[j] = s_rwin[base + OFF9(j)]; acc9[j] = 0.f; }
                    #pragma unroll
                    for (int i9 = 0; i9 < 9; i9++) {
                        #pragma unroll
                        for (int j9 = i9; j9 < 9; j9++) {
                            float v = g_S45[TIDX(i9, j9) * NLOC + m];
                            acc9[i9] += v * pn[j9];
                            if (j9 > i9) acc9[j9] += v * pn[i9];
                        }
                    }
                    #pragma unroll
                    for (int i9 = 0; i9 < 9; i9++) {
                        atomicAdd(&s_wwin[base + OFF9(i9)], -acc9[i9]);
                        dD1 -= (double)acc9[i9] * (double)pn[i9];
                    }
                } else {
                    #pragma unroll
                    for (int j = 0; j < 9; j++) { pn[j] = g_r[ind + OFF9(j)]; acc9[j] = 0.f; }
                    #pragma unroll
                    for (int i9 = 0; i9 < 9; i9++) {
                        #pragma unroll
                        for (int j9 = i9; j9 < 9; j9++) {
                            float v = g_S45[TIDX(i9, j9) * NLOC + m];
                            acc9[i9] += v * pn[j9];
                            if (j9 > i9) acc9[j9] += v * pn[i9];
                        }
                    }
                    #pragma unroll
                    for (int i9 = 0; i9 < 9; i9++) {
                        atomicAdd(&g_w[ind + OFF9(i9)], -acc9[i9]);
                        dD1 -= (double)acc9[i9] * (double)pn[i9];
                    }
                }
            }
            __syncthreads();
            if (useWin) {
                for (int i = tid; i < wsz; i += TPB) {
                    float v = s_wwin[i];
                    if (v != 0.f) atomicAdd(&g_w[w0 + i], v);
                }
            }
            double2 gd = bred2(dG, dD1, sm2);
            if (tid == 0) g_dot1[blockIdx.x] = gd;
        }
        gbar(ep);

        // Phase 2: CSC gather of Lv; IU (sorted); delta partials
        {
            double dD = 0.0;
            {
                float acc = 0.f;
                int k = cb0;
                for (; k + 4 <= cb1; k += 4) {
                    int2 e0 = g_pairC[k],     e1 = g_pairC[k + 1];
                    int2 e2 = g_pairC[k + 2], e3 = g_pairC[k + 3];
                    acc += __int_as_float(e0.y) * g_Lv[e0.x]
                         + __int_as_float(e1.y) * g_Lv[e1.x]
                         + __int_as_float(e2.y) * g_Lv[e2.x]
                         + __int_as_float(e3.y) * g_Lv[e3.x];
                }
                for (; k < cb1; k++) {
                    int2 e = g_pairC[k];
                    acc += __int_as_float(e.y) * g_Lv[e.x];
                }
                atomicAdd(&g_w[gtid], -acc);
                dD -= (double)acc * (double)r_reg;
            }
            if (tid < MPB) {
                int ind2 = g_iInd[m];
                float rind = g_r[ind2];
                float acc2 = 0.f;
                #pragma unroll
                for (int l = 0; l < KIU; l++) {
                    float wv = g_Wiu[l * NLOC + m];
                    int nb   = g_iuNbT[l * NLOC + m];
                    float rnb = g_r[nb];
                    acc2 += wv * rnb;
                    atomicAdd(&g_w[nb], -wv * rind);
                    dD -= (double)(wv * rind) * (double)rnb;
                }
                atomicAdd(&g_w[ind2], -acc2);
                dD -= (double)acc2 * (double)rind;
            }
            dD = bred(dD, sred);
            if (tid == 0) g_dot2[blockIdx.x] = dD;
        }
        gbar(ep);

        // Phase U: reduce; alpha/beta; register-resident update; reset w
        {
            double gamma = 0.0, delta = 0.0;
            if (tid < NBLK) {
                double2 gd = g_dot1[tid];
                gamma = gd.x;
                delta = gd.y + g_dot2[tid];
            }
            double2 gd = bred2(gamma, delta, sm2);
            if (tid == 0) {
                gamma = gd.x; delta = gd.y;
                double beta, alpha;
                if (it == 0) {
                    beta = 0.0;
                    alpha = gamma / delta;
                } else {
                    beta = gamma / s_gamma_prev;
                    alpha = gamma / (delta - beta * gamma / s_alpha_prev);
                }
                s_alpha = alpha; s_beta = beta;
                s_gamma_prev = gamma; s_alpha_prev = alpha;
            }
            __syncthreads();
            float alpha = (float)s_alpha;
            float beta  = (float)s_beta;
            float wi = g_w[gtid];
            g_w[gtid] = 0.f;
            if (it == 0) { p_reg = r_reg; s_reg = wi; }
            else {
                p_reg = r_reg + beta * p_reg;
                s_reg = wi + beta * s_reg;
            }
            x_reg += alpha * p_reg;
            r_reg = r_reg - alpha * s_reg;
            g_r[gtid] = r_reg;
            if (it == CG_STEPS - 1) x[gtid] = x_reg;
        }
        if (it + 1 < CG_STEPS) gbar(ep);
    }

    // ---- exit: last block resets barrier sense for the next graph replay
    __syncthreads();
    if (tid == 0) {
        __threadfence();
        if (atomicAdd(&g_exit, 1u) == NBLK - 1) {
            g_exit = 0u;
            g_sense = 0u;
            __threadfence();
        }
    }
}

// ---------------- host launch ----------------
extern "C" void kernel_launch(void* const* d_in, const int* in_sizes, int n_in,
                              void* d_out, int out_size) {
    const float* CMw    = (const float*)d_in[0];
    const float* LOCw   = (const float*)d_in[1];
    const float* IUw    = (const float*)d_in[2];
    const float* KUw    = (const float*)d_in[3];
    const float* lmbda  = (const float*)d_in[4];
    const float* kToUcf = (const float*)d_in[5];
    const float* known  = (const float*)d_in[6];
    const float* kToU   = (const float*)d_in[7];
    const float* Wd     = (const float*)d_in[8];
    const float* LF     = (const float*)d_in[9];
    const float* IUf    = (const float*)d_in[10];
    const int*   wrow   = (const int*)d_in[11];
    const int*   wcol   = (const int*)d_in[12];
    const int*   locInd = (const int*)d_in[13];
    const int*   iuInd  = (const int*)d_in[14];
    const int*   iuNb   = (const int*)d_in[15];
    float* x = (float*)d_out;

    k_all<<<NBLK, TPB>>>(x, CMw, LOCw, IUw, KUw, lmbda, kToUcf, known, kToU,
                         Wd, LF, IUf, wrow, wcol, locInd, iuInd, iuNb);
}

// round 10
// speedup vs baseline: 1.0629x; 1.0629x over previous
#include <cuda_runtime.h>

// ---------------- problem constants (fixed by dataset) ----------------
#define NPIX 147456        // 384*384
#define W384 384
#define NNZC 1474560       // NPIX/2 * 20
#define NLOC 73728         // NPIX/2
#define KIU  5
#define CG_STEPS 30

#define TPB   512
#define NBLK  288          // 288*512 == NPIX exactly
#define MPB   256          // matting pixels per block (NLOC / NBLK)
#define NWARP (TPB / 32)

// ---------------- device scratch (static only) ----------------
__device__ int2  g_pairR[NNZC];        // CSR-sorted {col, val-bits}
__device__ int2  g_pairC[NNZC];        // CSC-sorted {row, val-bits}
__device__ int   g_ptrR[NPIX + 1];
__device__ int   g_ptrC[NPIX + 1];
__device__ int   g_cntR[NPIX];
__device__ int   g_cntC[NPIX];
__device__ int   g_tmpR[NPIX];
__device__ int   g_tmpC[NPIX];
__device__ int   g_btot[288];
__device__ int   g_boff[288];

__device__ float g_rs_cm[NPIX];
__device__ float g_D[NPIX];
__device__ float g_S81[81 * NLOC];     // matting blocks [(i*9+j)*NLOC + m]
__device__ float g_Wiu[KIU * NLOC];    // [l*NLOC + k]
__device__ int   g_iuNbT[KIU * NLOC];  // transposed neighbor indices
__device__ float g_r[NPIX];
__device__ float g_w[NPIX];            // w = A r accumulator
__device__ float g_Lv[NPIX];
__device__ double2 g_dotGD[NBLK];      // {gamma, deltaA} partials
__device__ double  g_dotD2[NBLK];      // delta partials (phase C)

__device__ unsigned g_count;
__device__ volatile unsigned g_sense;

// ---------------- helpers ----------------
__device__ __forceinline__ int OFF9(int i) {
    int a = i / 3, b = i % 3;
    return (a - 1) + (b - 1) * W384;
}

__device__ __forceinline__ double bred(double v, double* sm) {
    int lane = threadIdx.x & 31, w = threadIdx.x >> 5;
    #pragma unroll
    for (int o = 16; o > 0; o >>= 1) v += __shfl_down_sync(0xffffffffu, v, o);
    if (lane == 0) sm[w] = v;
    __syncthreads();
    if (w == 0) {
        v = (lane < NWARP) ? sm[lane] : 0.0;
        #pragma unroll
        for (int o = 8; o > 0; o >>= 1) v += __shfl_down_sync(0xffffu, v, o);
    }
    __syncthreads();
    return v; // valid on thread 0
}

__device__ __forceinline__ double2 bred2(double a, double b, double2* sm2) {
    int lane = threadIdx.x & 31, w = threadIdx.x >> 5;
    #pragma unroll
    for (int o = 16; o > 0; o >>= 1) {
        a += __shfl_down_sync(0xffffffffu, a, o);
        b += __shfl_down_sync(0xffffffffu, b, o);
    }
    if (lane == 0) sm2[w] = make_double2(a, b);
    __syncthreads();
    if (w == 0) {
        double2 t = (lane < NWARP) ? sm2[lane] : make_double2(0.0, 0.0);
        a = t.x; b = t.y;
        #pragma unroll
        for (int o = 8; o > 0; o >>= 1) {
            a += __shfl_down_sync(0xffffu, a, o);
            b += __shfl_down_sync(0xffffu, b, o);
        }
    }
    __syncthreads();
    return make_double2(a, b);
}

__device__ __forceinline__ void gbar(unsigned &ep) {
    ep++;
    __syncthreads();
    if (threadIdx.x == 0) {
        __threadfence();
        if (atomicAdd(&g_count, 1u) == NBLK - 1) {
            g_count = 0;
            __threadfence();
            g_sense = ep;
        } else {
            while (g_sense != ep) { __nanosleep(32); }
            __threadfence();
        }
    }
    __syncthreads();
}

// ---------------- setup kernels ----------------
__global__ void k_z() {
    int i = blockIdx.x * blockDim.x + threadIdx.x;
    if (i < NPIX) {
        g_cntR[i] = 0; g_cntC[i] = 0; g_tmpR[i] = 0; g_tmpC[i] = 0;
        g_rs_cm[i] = 0.f; g_D[i] = 0.f;
    }
    if (i == 0) { g_count = 0; g_sense = 0; }
}

__global__ void k_cnt(const float* __restrict__ CMw, const float* __restrict__ Wd,
                      const int* __restrict__ row, const int* __restrict__ col) {
    int k = blockIdx.x * blockDim.x + threadIdx.x;
    if (k >= NNZC) return;
    int r = row[k], c = col[k];
    float cv = CMw[r] * Wd[k];
    atomicAdd(&g_rs_cm[r], cv);
    atomicAdd(&g_cntR[r], 1);
    atomicAdd(&g_cntC[c], 1);
}

// 288 blocks x 1024: blocks 0..143 scan cntR, 144..287 scan cntC (within-block)
__global__ void k_scanA() {
    __shared__ int sm[1024];
    int half = blockIdx.x / 144;
    int blk  = blockIdx.x % 144;
    int gi   = blk * 1024 + threadIdx.x;
    int* cnt = half ? g_cntC : g_cntR;
    int* ptr = half ? g_ptrC : g_ptrR;
    int v = cnt[gi];
    sm[threadIdx.x] = v;
    __syncthreads();
    for (int o = 1; o < 1024; o <<= 1) {
        int t = (threadIdx.x >= o) ? sm[threadIdx.x - o] : 0;
        __syncthreads();
        sm[threadIdx.x] += t;
        __syncthreads();
    }
    ptr[gi] = sm[threadIdx.x] - v;
    if (threadIdx.x == 1023) g_btot[blockIdx.x] = sm[1023];
}

__global__ void k_scanB() {
    __shared__ int sm[288];
    int t = threadIdx.x;
    int v = (t < 288) ? g_btot[t] : 0;
    if (t < 288) sm[t] = v;
    __syncthreads();
    for (int o = 1; o < 288; o <<= 1) {
        int add = 0;
        if (t < 288 && t >= o) add = sm[t - o];
        __syncthreads();
        if (t < 288) sm[t] += add;
        __syncthreads();
    }
    if (t < 288) {
        int ex = sm[t] - v;
        int base = (t >= 144) ? sm[143] : 0;
        g_boff[t] = ex - base;
    }
}

__global__ void k_scanC() {
    int half = blockIdx.x / 144;
    int blk  = blockIdx.x % 144;
    int gi   = blk * 1024 + threadIdx.x;
    int* ptr = half ? g_ptrC : g_ptrR;
    ptr[gi] += g_boff[blockIdx.x];
    if (blockIdx.x == 0 && threadIdx.x == 0) {
        g_ptrR[NPIX] = NNZC;
        g_ptrC[NPIX] = NNZC;
    }
}

__global__ void k_scatter(const float* __restrict__ CMw, const float* __restrict__ Wd,
                          const int* __restrict__ row, const int* __restrict__ col) {
    int k = blockIdx.x * blockDim.x + threadIdx.x;
    if (k >= NNZC) return;
    int r = row[k], c = col[k];
    int vb = __float_as_int(CMw[r] * Wd[k]);
    int p1 = g_ptrR[r] + atomicAdd(&g_tmpR[r], 1);
    g_pairR[p1] = make_int2(c, vb);
    int p2 = g_ptrC[c] + atomicAdd(&g_tmpC[c], 1);
    g_pairC[p2] = make_int2(r, vb);
}

// matting blocks (full 81 coefficients): one thread per unknown pixel
__global__ void k_p2(const float* __restrict__ LOCw, const float* __restrict__ LF,
                     const int* __restrict__ inInd) {
    int m = blockIdx.x * blockDim.x + threadIdx.x;
    if (m >= NLOC) return;
    int ind = inInd[m];
    float w = LOCw[ind];
    #pragma unroll
    for (int a = 0; a < 9; a++) {
        float rowsum = 0.f;
        #pragma unroll
        for (int b2 = 0; b2 < 9; b2++) {
            float s = 0.5f * w * (LF[(b2 * 9 + a) * NLOC + m] + LF[(a * 9 + b2) * NLOC + m]);
            g_S81[(a * 9 + b2) * NLOC + m] = s;
            rowsum += s;
        }
        atomicAdd(&g_D[ind + OFF9(a)], rowsum);
    }
}

__global__ void k_p3(const float* __restrict__ IUw, const float* __restrict__ IUf,
                     const int* __restrict__ inInd, const int* __restrict__ nbInd) {
    int k = blockIdx.x * blockDim.x + threadIdx.x;
    if (k >= NLOC) return;
    int ind = inInd[k];
    float w = IUw[ind];
    #pragma unroll
    for (int l = 0; l < KIU; l++) {
        float wv = 0.5f * w * IUf[k * KIU + l];
        int nb = nbInd[k * KIU + l];
        g_Wiu[l * NLOC + k] = wv;
        g_iuNbT[l * NLOC + k] = nb;
        atomicAdd(&g_D[ind], wv);
        atomicAdd(&g_D[nb], wv);
    }
}

__global__ void k_p4(const float* __restrict__ KUw, const float* __restrict__ kToUconf,
                     const float* __restrict__ known, const float* __restrict__ kToU,
                     const float* __restrict__ lmbda, float* __restrict__ x) {
    int i = blockIdx.x * blockDim.x + threadIdx.x;
    if (i >= NPIX) return;
    float dk = KUw[i] * kToUconf[i] + lmbda[0] * known[i];
    float b  = dk * kToU[i];
    g_D[i] += dk;
    g_r[i] = b;     // r0 = b (x0 = 0)
    x[i] = 0.f;
}

// ---------------- persistent single-reduction CG kernel ----------------
__global__ void __launch_bounds__(TPB, 2) k_cg(
    float* __restrict__ x,
    const int* __restrict__ locInd,
    const int* __restrict__ iuInd)
{
    __shared__ double2 sm2[NWARP];
    __shared__ double sred[NWARP];
    __shared__ double s_alpha, s_beta, s_gamma_prev, s_alpha_prev;
    const int tid  = threadIdx.x;
    const int gtid = blockIdx.x * TPB + tid;     // always < NPIX
    const int m    = blockIdx.x * MPB + tid;     // matting pixel if tid < MPB
    unsigned ep = 0;

    float r_reg = g_r[gtid];
    float p_reg = 0.f, s_reg = 0.f;
    const float rc = g_rs_cm[gtid];
    const float Di = g_D[gtid];
    const int rb0 = g_ptrR[gtid], rb1 = g_ptrR[gtid + 1];
    const int cb0 = g_ptrC[gtid], cb1 = g_ptrC[gtid + 1];

    for (int it = 0; it < CG_STEPS; ++it) {
        // ---- Phase A: CSR gather -> Lv -> w_init; gamma/delta partials
        {
            float acc = 0.f;
            int k = rb0;
            for (; k + 4 <= rb1; k += 4) {
                int2 e0 = __ldcs(&g_pairR[k]),     e1 = __ldcs(&g_pairR[k + 1]);
                int2 e2 = __ldcs(&g_pairR[k + 2]), e3 = __ldcs(&g_pairR[k + 3]);
                acc += __int_as_float(e0.y) * g_r[e0.x]
                     + __int_as_float(e1.y) * g_r[e1.x]
                     + __int_as_float(e2.y) * g_r[e2.x]
                     + __int_as_float(e3.y) * g_r[e3.x];
            }
            for (; k < rb1; k++) {
                int2 e = __ldcs(&g_pairR[k]);
                acc += __int_as_float(e.y) * g_r[e.x];
            }
            float lv = rc * r_reg - acc;
            g_Lv[gtid] = lv;
            float wi = rc * lv + Di * r_reg;
            g_w[gtid] = wi;
            double2 gd = bred2((double)r_reg * (double)r_reg,
                               (double)r_reg * (double)wi, sm2);
            if (tid == 0) g_dotGD[blockIdx.x] = gd;
        }
        gbar(ep);

        // ---- Phase C: CSC gather + matting + IU scatters; delta partials
        {
            double dD = 0.0;
            {
                float acc = 0.f;
                int k = cb0;
                for (; k + 4 <= cb1; k += 4) {
                    int2 e0 = __ldcs(&g_pairC[k]),     e1 = __ldcs(&g_pairC[k + 1]);
                    int2 e2 = __ldcs(&g_pairC[k + 2]), e3 = __ldcs(&g_pairC[k + 3]);
                    acc += __int_as_float(e0.y) * g_Lv[e0.x]
                         + __int_as_float(e1.y) * g_Lv[e1.x]
                         + __int_as_float(e2.y) * g_Lv[e2.x]
                         + __int_as_float(e3.y) * g_Lv[e3.x];
                }
                for (; k < cb1; k++) {
                    int2 e = __ldcs(&g_pairC[k]);
                    acc += __int_as_float(e.y) * g_Lv[e.x];
                }
                atomicAdd(&g_w[gtid], -acc);
                dD -= (double)acc * (double)r_reg;
            }
            if (tid < MPB) {
                // matting 9x9 block: full 81 coefficients, one acc at a time
                int ind = locInd[m];
                float pn[9];
                #pragma unroll
                for (int j = 0; j < 9; j++) pn[j] = g_r[ind + OFF9(j)];
                #pragma unroll
                for (int i9 = 0; i9 < 9; i9++) {
                    float acc = 0.f;
                    #pragma unroll
                    for (int j9 = 0; j9 < 9; j9++)
                        acc += __ldcs(&g_S81[(i9 * 9 + j9) * NLOC + m]) * pn[j9];
                    atomicAdd(&g_w[ind + OFF9(i9)], -acc);
                    dD -= (double)acc * (double)pn[i9];
                }
                // IU KNN
                int ind2 = iuInd[m];
                float rind = g_r[ind2];
                float acc2 = 0.f;
                #pragma unroll
                for (int l = 0; l < KIU; l++) {
                    float wv = __ldcs(&g_Wiu[l * NLOC + m]);
                    int nb   = __ldcs(&g_iuNbT[l * NLOC + m]);
                    float rnb = g_r[nb];
                    acc2 += wv * rnb;
                    atomicAdd(&g_w[nb], -wv * rind);
                    dD -= (double)(wv * rind) * (double)rnb;
                }
                atomicAdd(&g_w[ind2], -acc2);
                dD -= (double)acc2 * (double)rind;
            }
            dD = bred(dD, sred);
            if (tid == 0) g_dotD2[blockIdx.x] = dD;
        }
        gbar(ep);

        // ---- Phase U: reduce gamma/delta; alpha,beta; update
        {
            double gamma = 0.0, delta = 0.0;
            if (tid < NBLK) {
                double2 gd = g_dotGD[tid];
                gamma = gd.x;
                delta = gd.y + g_dotD2[tid];
            }
            double2 gd = bred2(gamma, delta, sm2);
            if (tid == 0) {
                gamma = gd.x; delta = gd.y;
                double beta, alpha;
                if (it == 0) {
                    beta = 0.0;
                    alpha = gamma / delta;
                } else {
                    beta = gamma / s_gamma_prev;
                    alpha = gamma / (delta - beta * gamma / s_alpha_prev);
                }
                s_alpha = alpha; s_beta = beta;
                s_gamma_prev = gamma; s_alpha_prev = alpha;
            }
            __syncthreads();
            float alpha = (float)s_alpha;
            float beta  = (float)s_beta;
            float wi = g_w[gtid];
            if (it == 0) { p_reg = r_reg; s_reg = wi; }
            else {
                p_reg = r_reg + beta * p_reg;
                s_reg = wi + beta * s_reg;
            }
            x[gtid] += alpha * p_reg;
            r_reg = r_reg - alpha * s_reg;
            g_r[gtid] = r_reg;
        }
        if (it + 1 < CG_STEPS) gbar(ep);
    }
}

// ---------------- host launch ----------------
extern "C" void kernel_launch(void* const* d_in, const int* in_sizes, int n_in,
                              void* d_out, int out_size) {
    const float* CMw    = (const float*)d_in[0];
    const float* LOCw   = (const float*)d_in[1];
    const float* IUw    = (const float*)d_in[2];
    const float* KUw    = (const float*)d_in[3];
    const float* lmbda  = (const float*)d_in[4];
    const float* kToUcf = (const float*)d_in[5];
    const float* known  = (const float*)d_in[6];
    const float* kToU   = (const float*)d_in[7];
    const float* Wd     = (const float*)d_in[8];
    const float* LF     = (const float*)d_in[9];
    const float* IUf    = (const float*)d_in[10];
    const int*   wrow   = (const int*)d_in[11];
    const int*   wcol   = (const int*)d_in[12];
    const int*   locInd = (const int*)d_in[13];
    const int*   iuInd  = (const int*)d_in[14];
    const int*   iuNb   = (const int*)d_in[15];
    float* x = (float*)d_out;

    const int gN   = (NPIX + 255) / 256;
    const int gNNZ = (NNZC + 255) / 256;
    const int gL   = (NLOC + 255) / 256;

    k_z<<<gN, 256>>>();
    k_cnt<<<gNNZ, 256>>>(CMw, Wd, wrow, wcol);
    k_scanA<<<288, 1024>>>();
    k_scanB<<<1, 320>>>();
    k_scanC<<<288, 1024>>>();
    k_scatter<<<gNNZ, 256>>>(CMw, Wd, wrow, wcol);
    k_p2<<<gL, 256>>>(LOCw, LF, locInd);
    k_p3<<<gL, 256>>>(IUw, IUf, iuInd, iuNb);
    k_p4<<<gN, 256>>>(KUw, kToUcf, known, kToU, lmbda, x);
    k_cg<<<NBLK, TPB>>>(x, locInd, iuInd);
}

// round 11
// speedup vs baseline: 1.1627x; 1.0939x over previous
#include <cuda_runtime.h>

// ---------------- problem constants (fixed by dataset) ----------------
#define NPIX 147456        // 384*384
#define W384 384
#define NNZC 1474560       // NPIX/2 * 20
#define NLOC 73728         // NPIX/2
#define KIU  5
#define CG_STEPS 30

#define TPB   512
#define NBLK  288          // 288*512 == NPIX exactly
#define MPB   256          // matting pixels per block (NLOC / NBLK)
#define NWARP (TPB / 32)

// ---------------- device scratch (static only) ----------------
__device__ int2  g_pairR[NNZC];        // CSR-sorted {col, val-bits}
__device__ int2  g_pairC[NNZC];        // CSC-sorted {row, val-bits}
__device__ int   g_ptrR[NPIX + 1];
__device__ int   g_ptrC[NPIX + 1];
__device__ int   g_ptrM[NPIX];
__device__ int   g_ptrI[NPIX];
__device__ int   g_cntR[NPIX];
__device__ int   g_cntC[NPIX];
__device__ int   g_cntM[NPIX];
__device__ int   g_cntI[NPIX];
__device__ int   g_tmpR[NPIX];
__device__ int   g_tmpC[NPIX];
__device__ int   g_tmpM[NPIX];
__device__ int   g_tmpI[NPIX];
__device__ int   g_btot[576];
__device__ int   g_boff[576];

__device__ int   g_mInd[NLOC];         // matting pixel indices, sorted ascending
__device__ int   g_iInd[NLOC];         // IU pixel indices, sorted ascending
__device__ float g_rs_cm[NPIX];
__device__ float g_D[NPIX];
__device__ float g_S45[45 * NLOC];     // symmetric matting blocks [t*NLOC + sorted_pos]
__device__ float g_Wiu[KIU * NLOC];    // [l*NLOC + sorted_pos]
__device__ int   g_iuNbT[KIU * NLOC];  // [l*NLOC + sorted_pos]
__device__ float g_r[NPIX];
__device__ float g_w[NPIX];            // w = A r accumulator
__device__ float g_Lv[NPIX];
__device__ double2 g_dotGD[NBLK];      // {gamma, deltaA} partials
__device__ double  g_dotD2[NBLK];      // delta partials (phase C)

__device__ unsigned g_count;
__device__ volatile unsigned g_sense;

// ---------------- helpers ----------------
__device__ __forceinline__ int OFF9(int i) {
    int a = i / 3, b = i % 3;
    return (a - 1) + (b - 1) * W384;
}
__device__ __forceinline__ int TIDX(int i, int j) {
    return 9 * i - (i * (i - 1)) / 2 + (j - i);
}

__device__ __forceinline__ double bred(double v, double* sm) {
    int lane = threadIdx.x & 31, w = threadIdx.x >> 5;
    #pragma unroll
    for (int o = 16; o > 0; o >>= 1) v += __shfl_down_sync(0xffffffffu, v, o);
    if (lane == 0) sm[w] = v;
    __syncthreads();
    if (w == 0) {
        v = (lane < NWARP) ? sm[lane] : 0.0;
        #pragma unroll
        for (int o = 8; o > 0; o >>= 1) v += __shfl_down_sync(0xffffu, v, o);
    }
    __syncthreads();
    return v; // valid on thread 0
}

__device__ __forceinline__ double2 bred2(double a, double b, double2* sm2) {
    int lane = threadIdx.x & 31, w = threadIdx.x >> 5;
    #pragma unroll
    for (int o = 16; o > 0; o >>= 1) {
        a += __shfl_down_sync(0xffffffffu, a, o);
        b += __shfl_down_sync(0xffffffffu, b, o);
    }
    if (lane == 0) sm2[w] = make_double2(a, b);
    __syncthreads();
    if (w == 0) {
        double2 t = (lane < NWARP) ? sm2[lane] : make_double2(0.0, 0.0);
        a = t.x; b = t.y;
        #pragma unroll
        for (int o = 8; o > 0; o >>= 1) {
            a += __shfl_down_sync(0xffffu, a, o);
            b += __shfl_down_sync(0xffffu, b, o);
        }
    }
    __syncthreads();
    return make_double2(a, b);
}

__device__ __forceinline__ void gbar(unsigned &ep) {
    ep++;
    __syncthreads();
    if (threadIdx.x == 0) {
        __threadfence();
        if (atomicAdd(&g_count, 1u) == NBLK - 1) {
            g_count = 0;
            __threadfence();
            g_sense = ep;
        } else {
            while (g_sense != ep) { __nanosleep(32); }
            __threadfence();
        }
    }
    __syncthreads();
}

// ---------------- setup kernels ----------------
__global__ void k_z() {
    int i = blockIdx.x * blockDim.x + threadIdx.x;
    if (i < NPIX) {
        g_cntR[i] = 0; g_cntC[i] = 0; g_cntM[i] = 0; g_cntI[i] = 0;
        g_tmpR[i] = 0; g_tmpC[i] = 0; g_tmpM[i] = 0; g_tmpI[i] = 0;
        g_rs_cm[i] = 0.f; g_D[i] = 0.f;
    }
    if (i == 0) { g_count = 0; g_sense = 0; }
}

__global__ void k_cnt(const float* __restrict__ CMw, const float* __restrict__ Wd,
                      const int* __restrict__ row, const int* __restrict__ col,
                      const int* __restrict__ locInd, const int* __restrict__ iuInd) {
    int k = blockIdx.x * blockDim.x + threadIdx.x;
    if (k < NLOC) {
        atomicAdd(&g_cntM[locInd[k]], 1);
        atomicAdd(&g_cntI[iuInd[k]], 1);
    }
    if (k >= NNZC) return;
    int r = row[k], c = col[k];
    float cv = CMw[r] * Wd[k];
    atomicAdd(&g_rs_cm[r], cv);
    atomicAdd(&g_cntR[r], 1);
    atomicAdd(&g_cntC[c], 1);
}

// 576 blocks x 1024: segments of 144 blocks scan cntR / cntC / cntM / cntI
__global__ void k_scanA() {
    __shared__ int sm[1024];
    int seg = blockIdx.x / 144;
    int blk = blockIdx.x % 144;
    int gi  = blk * 1024 + threadIdx.x;
    int* cnt = (seg == 0) ? g_cntR : (seg == 1) ? g_cntC : (seg == 2) ? g_cntM : g_cntI;
    int* ptr = (seg == 0) ? g_ptrR : (seg == 1) ? g_ptrC : (seg == 2) ? g_ptrM : g_ptrI;
    int v = cnt[gi];
    sm[threadIdx.x] = v;
    __syncthreads();
    for (int o = 1; o < 1024; o <<= 1) {
        int t = (threadIdx.x >= o) ? sm[threadIdx.x - o] : 0;
        __syncthreads();
        sm[threadIdx.x] += t;
        __syncthreads();
    }
    ptr[gi] = sm[threadIdx.x] - v;
    if (threadIdx.x == 1023) g_btot[blockIdx.x] = sm[1023];
}

// per-segment exclusive block offsets over 576 totals (4 segments of 144)
__global__ void k_scanB() {
    __shared__ int sm[576];
    int t = threadIdx.x;
    int v = (t < 576) ? g_btot[t] : 0;
    if (t < 576) sm[t] = v;
    __syncthreads();
    for (int o = 1; o < 576; o <<= 1) {
        int add = 0;
        if (t < 576 && t >= o) add = sm[t - o];
        __syncthreads();
        if (t < 576) sm[t] += add;
        __syncthreads();
    }
    if (t < 576) {
        int ex = sm[t] - v;                     // inclusive-all minus self
        int seg = t / 144;
        int base = (seg > 0) ? sm[seg * 144 - 1] : 0;
        g_boff[t] = ex - base;
    }
}

__global__ void k_scanC() {
    int seg = blockIdx.x / 144;
    int blk = blockIdx.x % 144;
    int gi  = blk * 1024 + threadIdx.x;
    int* ptr = (seg == 0) ? g_ptrR : (seg == 1) ? g_ptrC : (seg == 2) ? g_ptrM : g_ptrI;
    ptr[gi] += g_boff[blockIdx.x];
    if (blockIdx.x == 0 && threadIdx.x == 0) {
        g_ptrR[NPIX] = NNZC;
        g_ptrC[NPIX] = NNZC;
    }
}

__global__ void k_scatter(const float* __restrict__ CMw, const float* __restrict__ Wd,
                          const int* __restrict__ row, const int* __restrict__ col) {
    int k = blockIdx.x * blockDim.x + threadIdx.x;
    if (k >= NNZC) return;
    int r = row[k], c = col[k];
    int vb = __float_as_int(CMw[r] * Wd[k]);
    int p1 = g_ptrR[r] + atomicAdd(&g_tmpR[r], 1);
    g_pairR[p1] = make_int2(c, vb);
    int p2 = g_ptrC[c] + atomicAdd(&g_tmpC[c], 1);
    g_pairC[p2] = make_int2(r, vb);
}

// symmetric matting blocks written at SORTED positions
__global__ void k_p2(const float* __restrict__ LOCw, const float* __restrict__ LF,
                     const int* __restrict__ inInd) {
    int m0 = blockIdx.x * blockDim.x + threadIdx.x;
    if (m0 >= NLOC) return;
    int ind = inInd[m0];
    int pos = g_ptrM[ind] + atomicAdd(&g_tmpM[ind], 1);
    g_mInd[pos] = ind;
    float w = LOCw[ind];
    float rs[9];
    #pragma unroll
    for (int q = 0; q < 9; q++) rs[q] = 0.f;
    #pragma unroll
    for (int a = 0; a < 9; a++) {
        #pragma unroll
        for (int b2 = a; b2 < 9; b2++) {
            float s = 0.5f * w * (LF[(b2 * 9 + a) * NLOC + m0] + LF[(a * 9 + b2) * NLOC + m0]);
            g_S45[TIDX(a, b2) * NLOC + pos] = s;
            rs[a] += s;
            if (b2 > a) rs[b2] += s;
        }
    }
    #pragma unroll
    for (int q = 0; q < 9; q++) atomicAdd(&g_D[ind + OFF9(q)], rs[q]);
}

// IU weights written at SORTED positions
__global__ void k_p3(const float* __restrict__ IUw, const float* __restrict__ IUf,
                     const int* __restrict__ inInd, const int* __restrict__ nbInd) {
    int k = blockIdx.x * blockDim.x + threadIdx.x;
    if (k >= NLOC) return;
    int ind = inInd[k];
    int pos = g_ptrI[ind] + atomicAdd(&g_tmpI[ind], 1);
    g_iInd[pos] = ind;
    float w = IUw[ind];
    #pragma unroll
    for (int l = 0; l < KIU; l++) {
        float wv = 0.5f * w * IUf[k * KIU + l];
        int nb = nbInd[k * KIU + l];
        g_Wiu[l * NLOC + pos] = wv;
        g_iuNbT[l * NLOC + pos] = nb;
        atomicAdd(&g_D[ind], wv);
        atomicAdd(&g_D[nb], wv);
    }
}

__global__ void k_p4(const float* __restrict__ KUw, const float* __restrict__ kToUconf,
                     const float* __restrict__ known, const float* __restrict__ kToU,
                     const float* __restrict__ lmbda, float* __restrict__ x) {
    int i = blockIdx.x * blockDim.x + threadIdx.x;
    if (i >= NPIX) return;
    float dk = KUw[i] * kToUconf[i] + lmbda[0] * known[i];
    float b  = dk * kToU[i];
    g_D[i] += dk;
    g_r[i] = b;     // r0 = b (x0 = 0)
    x[i] = 0.f;
}

// ---------------- persistent single-reduction CG kernel ----------------
__global__ void __launch_bounds__(TPB, 2) k_cg(float* __restrict__ x)
{
    __shared__ double2 sm2[NWARP];
    __shared__ double sred[NWARP];
    __shared__ double s_alpha, s_beta, s_gamma_prev, s_alpha_prev;
    const int tid  = threadIdx.x;
    const int gtid = blockIdx.x * TPB + tid;     // always < NPIX
    const int m    = blockIdx.x * MPB + tid;     // sorted matting/IU slot if tid < MPB
    unsigned ep = 0;

    float r_reg = g_r[gtid];
    float p_reg = 0.f, s_reg = 0.f;
    const float rc = g_rs_cm[gtid];
    const float Di = g_D[gtid];
    const int rb0 = g_ptrR[gtid], rb1 = g_ptrR[gtid + 1];
    const int cb0 = g_ptrC[gtid], cb1 = g_ptrC[gtid + 1];

    for (int it = 0; it < CG_STEPS; ++it) {
        // ---- Phase A: CSR gather -> Lv -> w_init; gamma/delta partials
        {
            float acc = 0.f;
            int k = rb0;
            for (; k + 4 <= rb1; k += 4) {
                int2 e0 = __ldcs(&g_pairR[k]),     e1 = __ldcs(&g_pairR[k + 1]);
                int2 e2 = __ldcs(&g_pairR[k + 2]), e3 = __ldcs(&g_pairR[k + 3]);
                acc += __int_as_float(e0.y) * g_r[e0.x]
                     + __int_as_float(e1.y) * g_r[e1.x]
                     + __int_as_float(e2.y) * g_r[e2.x]
                     + __int_as_float(e3.y) * g_r[e3.x];
            }
            for (; k < rb1; k++) {
                int2 e = __ldcs(&g_pairR[k]);
                acc += __int_as_float(e.y) * g_r[e.x];
            }
            float lv = rc * r_reg - acc;
            g_Lv[gtid] = lv;
            float wi = rc * lv + Di * r_reg;
            g_w[gtid] = wi;
            double2 gd = bred2((double)r_reg * (double)r_reg,
                               (double)r_reg * (double)wi, sm2);
            if (tid == 0) g_dotGD[blockIdx.x] = gd;
        }
        gbar(ep);

        // ---- Phase C: CSC gather + matting (sorted) + IU (sorted); delta partials
        {
            double dD = 0.0;
            {
                float acc = 0.f;
                int k = cb0;
                for (; k + 4 <= cb1; k += 4) {
                    int2 e0 = __ldcs(&g_pairC[k]),     e1 = __ldcs(&g_pairC[k + 1]);
                    int2 e2 = __ldcs(&g_pairC[k + 2]), e3 = __ldcs(&g_pairC[k + 3]);
                    acc += __int_as_float(e0.y) * g_Lv[e0.x]
                         + __int_as_float(e1.y) * g_Lv[e1.x]
                         + __int_as_float(e2.y) * g_Lv[e2.x]
                         + __int_as_float(e3.y) * g_Lv[e3.x];
                }
                for (; k < cb1; k++) {
                    int2 e = __ldcs(&g_pairC[k]);
                    acc += __int_as_float(e.y) * g_Lv[e.x];
                }
                atomicAdd(&g_w[gtid], -acc);
                dD -= (double)acc * (double)r_reg;
            }
            if (tid < MPB) {
                // symmetric 9x9 matting block; lanes hit nearby pixels (sorted)
                int ind = g_mInd[m];
                float pn[9], acc9[9];
                #pragma unroll
                for (int j = 0; j < 9; j++) { pn[j] = g_r[ind + OFF9(j)]; acc9[j] = 0.f; }
                #pragma unroll
                for (int i9 = 0; i9 < 9; i9++) {
                    #pragma unroll
                    for (int j9 = i9; j9 < 9; j9++) {
                        float v = g_S45[TIDX(i9, j9) * NLOC + m];
                        acc9[i9] += v * pn[j9];
                        if (j9 > i9) acc9[j9] += v * pn[i9];
                    }
                }
                #pragma unroll
                for (int i9 = 0; i9 < 9; i9++) {
                    atomicAdd(&g_w[ind + OFF9(i9)], -acc9[i9]);
                    dD -= (double)acc9[i9] * (double)pn[i9];
                }
                // IU KNN (sorted by owning pixel)
                int ind2 = g_iInd[m];
                float rind = g_r[ind2];
                float acc2 = 0.f;
                #pragma unroll
                for (int l = 0; l < KIU; l++) {
                    float wv = g_Wiu[l * NLOC + m];
                    int nb   = g_iuNbT[l * NLOC + m];
                    float rnb = g_r[nb];
                    acc2 += wv * rnb;
                    atomicAdd(&g_w[nb], -wv * rind);
                    dD -= (double)(wv * rind) * (double)rnb;
                }
                atomicAdd(&g_w[ind2], -acc2);
                dD -= (double)acc2 * (double)rind;
            }
            dD = bred(dD, sred);
            if (tid == 0) g_dotD2[blockIdx.x] = dD;
        }
        gbar(ep);

        // ---- Phase U: reduce gamma/delta; alpha,beta; update
        {
            double gamma = 0.0, delta = 0.0;
            if (tid < NBLK) {
                double2 gd = g_dotGD[tid];
                gamma = gd.x;
                delta = gd.y + g_dotD2[tid];
            }
            double2 gd = bred2(gamma, delta, sm2);
            if (tid == 0) {
                gamma = gd.x; delta = gd.y;
                double beta, alpha;
                if (it == 0) {
                    beta = 0.0;
                    alpha = gamma / delta;
                } else {
                    beta = gamma / s_gamma_prev;
                    alpha = gamma / (delta - beta * gamma / s_alpha_prev);
                }
                s_alpha = alpha; s_beta = beta;
                s_gamma_prev = gamma; s_alpha_prev = alpha;
            }
            __syncthreads();
            float alpha = (float)s_alpha;
            float beta  = (float)s_beta;
            float wi = g_w[gtid];
            if (it == 0) { p_reg = r_reg; s_reg = wi; }
            else {
                p_reg = r_reg + beta * p_reg;
                s_reg = wi + beta * s_reg;
            }
            x[gtid] += alpha * p_reg;
            r_reg = r_reg - alpha * s_reg;
            g_r[gtid] = r_reg;
        }
        if (it + 1 < CG_STEPS) gbar(ep);
    }
}

// ---------------- host launch ----------------
extern "C" void kernel_launch(void* const* d_in, const int* in_sizes, int n_in,
                              void* d_out, int out_size) {
    const float* CMw    = (const float*)d_in[0];
    const float* LOCw   = (const float*)d_in[1];
    const float* IUw    = (const float*)d_in[2];
    const float* KUw    = (const float*)d_in[3];
    const float* lmbda  = (const float*)d_in[4];
    const float* kToUcf = (const float*)d_in[5];
    const float* known  = (const float*)d_in[6];
    const float* kToU   = (const float*)d_in[7];
    const float* Wd     = (const float*)d_in[8];
    const float* LF     = (const float*)d_in[9];
    const float* IUf    = (const float*)d_in[10];
    const int*   wrow   = (const int*)d_in[11];
    const int*   wcol   = (const int*)d_in[12];
    const int*   locInd = (const int*)d_in[13];
    const int*   iuInd  = (const int*)d_in[14];
    const int*   iuNb   = (const int*)d_in[15];
    float* x = (float*)d_out;

    const int gN   = (NPIX + 255) / 256;
    const int gNNZ = (NNZC + 255) / 256;
    const int gL   = (NLOC + 255) / 256;

    k_z<<<gN, 256>>>();
    k_cnt<<<gNNZ, 256>>>(CMw, Wd, wrow, wcol, locInd, iuInd);
    k_scanA<<<576, 1024>>>();
    k_scanB<<<1, 576>>>();
    k_scanC<<<576, 1024>>>();
    k_scatter<<<gNNZ, 256>>>(CMw, Wd, wrow, wcol);
    k_p2<<<gL, 256>>>(LOCw, LF, locInd);
    k_p3<<<gL, 256>>>(IUw, IUf, iuInd, iuNb);
    k_p4<<<gN, 256>>>(KUw, kToUcf, known, kToU, lmbda, x);
    k_cg<<<NBLK, TPB>>>(x);
}